// round 8
// baseline (speedup 1.0000x reference)
#include <cuda_runtime.h>

#define NTOT 131072
typedef unsigned long long ull;

// ---------- f32x2 helpers ----------
__device__ __forceinline__ ull dup2(float a) {
    ull r; asm("mov.b64 %0, {%1, %1};" : "=l"(r) : "f"(a)); return r;
}
__device__ __forceinline__ ull ffma2(ull a, ull b, ull c) {
    ull d; asm("fma.rn.f32x2 %0, %1, %2, %3;" : "=l"(d) : "l"(a), "l"(b), "l"(c)); return d;
}
__device__ __forceinline__ ull fadd2(ull a, ull b) {
    ull d; asm("add.rn.f32x2 %0, %1, %2;" : "=l"(d) : "l"(a), "l"(b)); return d;
}
__device__ __forceinline__ void f2unpack(float& lo, float& hi, ull v) {
    asm("mov.b64 {%0, %1}, %2;" : "=f"(lo), "=f"(hi) : "l"(v));
}

// ---------- scratch ----------
__device__ float4 g_xT4[NTOT * 32 / 4];
__device__ float4 g_t4[8515584 / 4];
#define g_xT ((float*)g_xT4)
#define g_t  ((float*)g_t4)

// ranks and t-offsets (t layout: [block][r][n], n fastest, 32 wide)
__constant__ int c_R[12]    = {64,64,64,64,64,64,64,64,64,52,32,20};
__constant__ int c_TOFF[12] = {0,4096,12288,28672,61440,126976,258048,520192,
                               1044480,2093056,3796992,5894144};
#define H_TOFF9 2093056          // zero region end (levels 0-8 atomic)

struct P { const float* u[12]; };

// ---------- transpose x: [B][N] -> [N][B] ----------
__global__ void k_transpose_in(const float* __restrict__ x) {
    __shared__ float tile[32][33];
    int i0 = blockIdx.x * 32;
    int tx = threadIdx.x, ty = threadIdx.y;
    tile[ty][tx] = x[(size_t)ty * NTOT + i0 + tx];
    __syncthreads();
    g_xT[(size_t)(i0 + ty) * 32 + tx] = tile[tx][ty];
}

__global__ void k_zero_t() {
    int i = blockIdx.x * blockDim.x + threadIdx.x;
    if (i < H_TOFF9 / 4) g_t4[i] = make_float4(0.f, 0.f, 0.f, 0.f);
}

// ---------- core 16-FFMA2 step: acc[j][c] += dup(a8[j]) * b2[c] ----------
__device__ __forceinline__ void step16(const float* __restrict__ a8,
                                       const ull* __restrict__ b2, ull* __restrict__ acc) {
    float4 A0 = *(const float4*)a8;
    float4 A1 = *(const float4*)(a8 + 4);
    ulonglong2 B = *(const ulonglong2*)b2;
    float av[8] = {A0.x, A0.y, A0.z, A0.w, A1.x, A1.y, A1.z, A1.w};
    #pragma unroll
    for (int j = 0; j < 8; j++) {
        ull ad = dup2(av[j]);
        acc[2*j]   = ffma2(ad, B.x, acc[2*j]);
        acc[2*j+1] = ffma2(ad, B.y, acc[2*j+1]);
    }
}

// ================= phase 1: t[block][r][n] = sum_s U[s][r] x[s][n] =================
// CTA = 256 thr (8 warps), slice = 128 s. Warp tile 32r x 32n, thread tile 8r x 4n.
__global__ void __launch_bounds__(256) k_p1(P p) {
    __shared__ __align__(16) ull  xs2[2048];   // x slice [s128][16 ull]  (16KB)
    __shared__ __align__(16) float us[8192];   // U slice [s128][64] / reduce buf (32KB)
    int tid = threadIdx.x, slice = blockIdx.x;
    int w = tid >> 5, lane = tid & 31, ri = lane >> 3, ni = lane & 7;

    {   // stage x (coalesced, n-pairs natural)
        const float4* src = g_xT4 + (size_t)slice * 1024;
        float4* d = (float4*)xs2;
        for (int i = tid; i < 1024; i += 256) d[i] = src[i];
    }

    #pragma unroll 1
    for (int l = 0; l < 12; l++) {
        int R = c_R[l];
        int rq = R / 4;
        __syncthreads();
        {   // stage U natural [s][64], zero-pad cols >= R
            const float4* u4 = (const float4*)p.u[l] + (size_t)slice * 128 * rq;
            float4* d = (float4*)us;
            for (int i = tid; i < 2048; i += 256) {
                int s = i >> 4, c4 = i & 15;
                d[i] = (c4 < rq) ? u4[s * rq + c4] : make_float4(0.f, 0.f, 0.f, 0.f);
            }
        }
        __syncthreads();

        ull acc[16];
        #pragma unroll
        for (int j = 0; j < 16; j++) acc[j] = 0;

        int sbeg, K, rbase, active = 1;
        if (l <= 9)      { rbase = (w >> 2) * 32; sbeg = (w & 3) * 32;               K = 32; }
        else if (l == 10){ rbase = 0;             sbeg = (w >> 2) * 64 + (w & 3)*16; K = 16; }
        else             { rbase = 0;             sbeg = (w & 3) * 32;               K = 32; active = (w < 4); }

        if (active) {
            #pragma unroll 2
            for (int k = 0; k < K; k++) {
                int s = sbeg + k;
                step16(us + s * 64 + rbase + ri * 8, xs2 + s * 16 + ni * 2, acc);
            }
        }

        if (l == 11) {
            if (w < 4) {   // direct store, block fully inside warp's K
                int block = slice * 4 + w;
                float* td = g_t + c_TOFF[11] + (size_t)block * 20 * 32;
                #pragma unroll
                for (int rr = 0; rr < 8; rr++) {
                    int r = ri * 8 + rr;
                    if (r < 20) {
                        #pragma unroll
                        for (int c = 0; c < 2; c++)
                            *(ull*)(td + r * 32 + ni * 4 + c * 2) = acc[rr * 2 + c];
                    }
                }
            }
        } else {
            __syncthreads();
            ull* red = (ull*)us;
            {
                ull* dst = red + w * 512 + lane * 16;
                #pragma unroll
                for (int j = 0; j < 16; j++) dst[j] = acc[j];
            }
            __syncthreads();
            // 4-way cross-warp reduce + store (1024 ull outputs, 4 per thread)
            #pragma unroll
            for (int q = 0; q < 4; q++) {
                int o = tid * 4 + q;
                int grp, r, n2;
                if (l <= 9) { r = o >> 4;  n2 = o & 15; grp = r >> 5; }
                else        { grp = o >> 9; r = (o >> 4) & 31; n2 = o & 15; }
                int rl = r & 31;
                int idx = ((rl >> 3) * 8 + (n2 >> 1)) * 16 + (rl & 7) * 2 + (n2 & 1);
                ull v = fadd2(fadd2(red[(grp*4+0)*512 + idx], red[(grp*4+1)*512 + idx]),
                              fadd2(red[(grp*4+2)*512 + idx], red[(grp*4+3)*512 + idx]));
                int n = n2 * 2;
                if (l <= 8) {
                    int block = slice >> (9 - l);
                    float* td = g_t + c_TOFF[l] + ((size_t)block * 64 + r) * 32 + n;
                    float lo, hi; f2unpack(lo, hi, v);
                    atomicAdd(td, lo); atomicAdd(td + 1, hi);
                } else if (l == 9) {
                    if (r < 52)
                        *(ull*)(g_t + c_TOFF[9] + ((size_t)slice * 52 + r) * 32 + n) = v;
                } else {  // l == 10
                    int block = slice * 2 + grp;
                    *(ull*)(g_t + c_TOFF[10] + ((size_t)block * 32 + r) * 32 + n) = v;
                }
            }
        }
    }
}

// ================= epilogue: y = leaf + sum_l s2 * U t_sib ; out transpose =================
// CTA = 256 thr (8 warps), slice = 128 s. Warp: s-tile st = w&3 (32 s), K-half kh = w>>2.
// acc (8s x 4n as 16 f32x2) lives in registers across leaf + all 12 levels.
__global__ void __launch_bounds__(256) k_epi(P p, const float* __restrict__ lb,
                                             const float* __restrict__ sc,
                                             float* __restrict__ out) {
    extern __shared__ __align__(16) char smraw[];
    float* ut = (float*)smraw;                 // 8448 fl: U^T [k][132] / lbt / y merge buf
    ull*  B2 = (ull*)(smraw + 33792);          // 2048 ull: xs (leaf) / ts2
    int tid = threadIdx.x, slice = blockIdx.x;
    int w = tid >> 5, lane = tid & 31, si = lane >> 3, ni = lane & 7;
    int st = w & 3, kh = w >> 2;
    int s0l = st * 32;

    {   // stage leaf blocks transposed: lbt[q][s][t], stride 36
        const float4* lb4 = (const float4*)lb + (size_t)slice * 1024;
        for (int i = tid; i < 1024; i += 256) {
            int q = i >> 8, t = (i >> 3) & 31, s4 = i & 7;
            float4 v = lb4[i];
            float* dst = ut + q * 1152 + (s4 * 4) * 36 + t;
            dst[0] = v.x; dst[36] = v.y; dst[72] = v.z; dst[108] = v.w;
        }
        const float4* xsrc = g_xT4 + (size_t)slice * 1024;
        float4* xd = (float4*)B2;
        for (int i = tid; i < 1024; i += 256) xd[i] = xsrc[i];
    }
    __syncthreads();

    ull acc[16];
    #pragma unroll
    for (int j = 0; j < 16; j++) acc[j] = 0;

    // leaf: y[t][n] = sum_s lb[t][s] x[s][n]; K split in halves of 16
    for (int k = kh * 16; k < kh * 16 + 16; k++)
        step16(ut + st * 1152 + k * 36 + si * 8, B2 + (st * 32 + k) * 16 + ni * 2, acc);

    float scv = __ldg(sc);
    float s2 = scv * scv;

    #pragma unroll 1
    for (int l = 0; l < 12; l++) {
        int R = c_R[l];
        int rq = R / 4;
        __syncthreads();
        {   // stage U transposed: ut[k][s], stride 132 (coalesced read, scatter write)
            const float4* u4 = (const float4*)p.u[l] + (size_t)slice * 128 * rq;
            for (int i = tid; i < 2048; i += 256) {
                int s = i >> 4, c4 = i & 15;
                if (c4 < rq) {
                    float4 v = u4[s * rq + c4];
                    float* dst = ut + (c4 * 4) * 132 + s;
                    dst[0] = v.x; dst[132] = v.y; dst[264] = v.z; dst[396] = v.w;
                }
            }
            // stage sibling t, scaled by s2, n-pair packed: ts2[(sib)][k][16 ull]
            const float4* tsrc; int nf4;
            if (l <= 8)      { int sib = (slice >> (9 - l)) ^ 1;
                               tsrc = (const float4*)(g_t + c_TOFF[l]) + (size_t)sib * 512; nf4 = 512; }
            else if (l == 9) { int sib = slice ^ 1;
                               tsrc = (const float4*)(g_t + c_TOFF[9]) + (size_t)sib * 416; nf4 = 416; }
            else if (l == 10){ tsrc = (const float4*)(g_t + c_TOFF[10]) + (size_t)slice * 512; nf4 = 512; }
            else             { tsrc = (const float4*)(g_t + c_TOFF[11]) + (size_t)slice * 640; nf4 = 640; }
            float4* td = (float4*)B2;
            for (int i = tid; i < nf4; i += 256) {
                float4 v = tsrc[i];
                v.x *= s2; v.y *= s2; v.z *= s2; v.w *= s2;
                td[i] = v;
            }
        }
        __syncthreads();

        int tsb = 0;
        if (l == 10)      tsb = ((st >> 1) ^ 1) * (32 * 16);
        else if (l == 11) tsb = (st ^ 1) * (20 * 16);

        int Kh = R / 2;
        int k0 = kh * Kh, k1 = k0 + Kh;
        for (int k = k0; k < k1; k++)
            step16(ut + k * 132 + s0l + si * 8, B2 + tsb + k * 16 + ni * 2, acc);
    }

    // ---- merge K-halves in one buffer (ut region, stride 34: 4352 <= 8448 fl) ----
    __syncthreads();
    float* yb = ut;
    if (kh == 1) {
        #pragma unroll
        for (int rr = 0; rr < 8; rr++) {
            int s = s0l + si * 8 + rr;
            #pragma unroll
            for (int c = 0; c < 2; c++)
                *(ull*)(yb + s * 34 + ni * 4 + c * 2) = acc[rr * 2 + c];
        }
    }
    __syncthreads();
    if (kh == 0) {
        #pragma unroll
        for (int rr = 0; rr < 8; rr++) {
            int s = s0l + si * 8 + rr;
            #pragma unroll
            for (int c = 0; c < 2; c++) {
                ull* pp = (ull*)(yb + s * 34 + ni * 4 + c * 2);
                *pp = fadd2(*pp, acc[rr * 2 + c]);
            }
        }
    }
    __syncthreads();
    // transpose-out: out[n][slice*128 + s] = yb[s][n]
    for (int i = tid; i < 4096; i += 256) {
        int n = i >> 7, s = i & 127;
        out[(size_t)n * NTOT + slice * 128 + s] = yb[s * 34 + n];
    }
}

// ---------- driver ----------
extern "C" void kernel_launch(void* const* d_in, const int* in_sizes, int n_in,
                              void* d_out, int out_size) {
    (void)in_sizes; (void)n_in; (void)out_size;
    const float* x  = (const float*)d_in[0];
    const float* lb = (const float*)d_in[1];
    const float* sc = (const float*)d_in[2];
    P p;
    for (int l = 0; l < 12; l++) p.u[l] = (const float*)d_in[3 + l];
    float* out = (float*)d_out;

    const int SMEM_EPI = 33792 + 16384;   // 50176 B
    cudaFuncSetAttribute(k_epi, cudaFuncAttributeMaxDynamicSharedMemorySize, SMEM_EPI);

    k_transpose_in<<<4096, dim3(32, 32)>>>(x);
    k_zero_t<<<(H_TOFF9 / 4 + 255) / 256, 256>>>();
    k_p1<<<1024, 256>>>(p);
    k_epi<<<1024, 256, SMEM_EPI>>>(p, lb, sc, out);
}

// round 10
// speedup vs baseline: 1.8423x; 1.8423x over previous
#include <cuda_runtime.h>
#include <cstdint>

#define NTOT 131072

__device__ __align__(16) float g_t[9170944];
__constant__ int c_OFF[12] = {0,4096,12288,28672,61440,126976,258048,520192,
                              1044480,2093056,3928064,6025216};
__constant__ int c_R[12] = {64,64,64,64,64,64,64,64,64,52,32,20};
#define ZERON 2093056   // levels 0-8 atomic region

struct P { const float* u[12]; };

// ---------- helpers ----------
__device__ __forceinline__ uint32_t cvtf32(float f) {
    uint32_t r; asm("cvt.rna.tf32.f32 %0, %1;" : "=r"(r) : "f"(f)); return r;
}
__device__ __forceinline__ uint4 cvt4(float4 v) {
    uint4 o; o.x = cvtf32(v.x); o.y = cvtf32(v.y); o.z = cvtf32(v.z); o.w = cvtf32(v.w);
    return o;
}
__device__ __forceinline__ void mma8(float* c, const uint32_t* a, uint32_t b0, uint32_t b1) {
    asm volatile("mma.sync.aligned.m16n8k8.row.col.f32.tf32.tf32.f32 "
        "{%0,%1,%2,%3}, {%4,%5,%6,%7}, {%8,%9}, {%0,%1,%2,%3};"
        : "+f"(c[0]), "+f"(c[1]), "+f"(c[2]), "+f"(c[3])
        : "r"(a[0]), "r"(a[1]), "r"(a[2]), "r"(a[3]), "r"(b0), "r"(b1));
}

__global__ void k_zero_t() {
    int i = blockIdx.x * blockDim.x + threadIdx.x;
    if (i < ZERON / 4) ((float4*)g_t)[i] = make_float4(0.f, 0.f, 0.f, 0.f);
}

// ================= phase 1: t'[n][r-stack] = x[n][s] * U[s][r], per 128-s slice =================
// smem: xs [32][132] (A, row-major), us [128][104] (B, col-major frag reads)
#define P1_SM ((4224 + 13312) * 4)
__global__ void __launch_bounds__(256) k_p1(P p, const float* __restrict__ x) {
    extern __shared__ __align__(16) float sm[];
    float* xs = sm;
    float* us = sm + 4224;
    const uint32_t* xsu = (const uint32_t*)xs;
    const uint32_t* usu = (const uint32_t*)us;
    int tid = threadIdx.x, w = tid >> 5, lane = tid & 31;
    int g = lane >> 2, t4 = lane & 3;
    int wm = w >> 2, wg = w & 3;
    int slice = blockIdx.x, s0 = slice * 128;

    for (int i = tid; i < 1024; i += 256) {               // xs[n][132]
        int n = i >> 5, s4 = i & 31;
        float4 v = *(const float4*)(x + (size_t)n * NTOT + s0 + 4 * s4);
        *(uint4*)(xs + n * 132 + 4 * s4) = cvt4(v);
    }

    #pragma unroll 1
    for (int L = 0; L < 12; L++) {
        int R = c_R[L], Rq = R >> 2;
        __syncthreads();
        if (L >= 9) {                                      // zero-fill (pad / off-diag)
            uint4 z = {0, 0, 0, 0};
            for (int i = tid; i < 3328; i += 256) ((uint4*)us)[i] = z;
            __syncthreads();
        }
        const float* U = p.u[L];
        for (int i = tid; i < 128 * Rq; i += 256) {        // us[s][104], col offset per level
            int s = i / Rq, r4 = i - s * Rq;
            float4 v = *(const float4*)(U + (size_t)(s0 + s) * R + 4 * r4);
            int col = (L <= 9) ? 4 * r4 : (L == 10 ? 32 * (s >> 6) + 4 * r4
                                                   : 24 * (s >> 5) + 4 * r4);
            *(uint4*)(us + s * 104 + col) = cvt4(v);
        }
        __syncthreads();

        int ntile = (L == 11) ? 3 : 2;
        int nb = (L == 11) ? 24 * wg : 16 * wg;
        int kc0 = 0, kc1 = 16;
        if (L == 10) { kc0 = 8 * (wg >> 1); kc1 = kc0 + 8; }
        if (L == 11) { kc0 = 4 * wg;        kc1 = kc0 + 4; }

        float acc[3][4];
        #pragma unroll
        for (int j = 0; j < 3; j++) { acc[j][0] = acc[j][1] = acc[j][2] = acc[j][3] = 0.f; }

        const uint32_t* X = xsu + 16 * wm * 132;
        for (int kc = kc0; kc < kc1; kc++) {
            uint32_t a[4];
            int ko = 8 * kc + t4;
            a[0] = X[g * 132 + ko];       a[1] = X[(g + 8) * 132 + ko];
            a[2] = X[g * 132 + ko + 4];   a[3] = X[(g + 8) * 132 + ko + 4];
            const uint32_t* B0 = usu + (8 * kc + t4) * 104;
            const uint32_t* B1 = usu + (8 * kc + t4 + 4) * 104;
            #pragma unroll
            for (int j = 0; j < 3; j++)
                if (j < ntile) {
                    int np = nb + 8 * j + g;
                    mma8(acc[j], a, B0[np], B1[np]);
                }
        }

        int n1 = 16 * wm + g;
        #pragma unroll
        for (int j = 0; j < 3; j++) {
            if (j < ntile) {
                int np = nb + 8 * j + 2 * t4;
                if (L <= 8) {
                    int blk = slice >> (9 - L);
                    float* d0 = g_t + c_OFF[L] + (size_t)blk * 2048;
                    atomicAdd(d0 + n1 * 64 + np,           acc[j][0]);
                    atomicAdd(d0 + n1 * 64 + np + 1,       acc[j][1]);
                    atomicAdd(d0 + (n1 + 8) * 64 + np,     acc[j][2]);
                    atomicAdd(d0 + (n1 + 8) * 64 + np + 1, acc[j][3]);
                } else if (L == 9) {
                    if (np < 56) {
                        float* d0 = g_t + c_OFF[9] + (size_t)slice * 1792;
                        *(float2*)(d0 + n1 * 56 + np)       = make_float2(acc[j][0], acc[j][1]);
                        *(float2*)(d0 + (n1 + 8) * 56 + np) = make_float2(acc[j][2], acc[j][3]);
                    }
                } else if (L == 10) {
                    int blk = slice * 2 + (np >> 5), r = np & 31;
                    float* d0 = g_t + c_OFF[10] + (size_t)blk * 1024;
                    *(float2*)(d0 + n1 * 32 + r)       = make_float2(acc[j][0], acc[j][1]);
                    *(float2*)(d0 + (n1 + 8) * 32 + r) = make_float2(acc[j][2], acc[j][3]);
                } else {
                    int blk = slice * 4 + wg, r = 8 * j + 2 * t4;
                    float* d0 = g_t + c_OFF[11] + (size_t)blk * 768;
                    *(float2*)(d0 + n1 * 24 + r)       = make_float2(acc[j][0], acc[j][1]);
                    *(float2*)(d0 + (n1 + 8) * 24 + r) = make_float2(acc[j][2], acc[j][3]);
                }
            }
        }
    }
}

// ================= epilogue: out[n][s] = leaf + sum_L t_sib[n][r] * U[s][r] =================
// smem region1: xs [32][132] then us [128][68]; region2: lbs 4x[32][36] then ts slots
#define E_SM ((8704 + 4608) * 4)
__global__ void __launch_bounds__(256) k_epi(P p, const float* __restrict__ lb,
                                             const float* __restrict__ x,
                                             const float* __restrict__ sc,
                                             float* __restrict__ out) {
    extern __shared__ __align__(16) float sm[];
    float* r1 = sm;
    float* r2 = sm + 8704;
    const uint32_t* r1u = (const uint32_t*)r1;
    const uint32_t* r2u = (const uint32_t*)r2;
    int tid = threadIdx.x, w = tid >> 5, lane = tid & 31;
    int g = lane >> 2, t4 = lane & 3;
    int wm = w >> 2, wg = w & 3;
    int slice = blockIdx.x, s0 = slice * 128;
    float scv = __ldg(sc), s2 = scv * scv;

    for (int i = tid; i < 1024; i += 256) {               // xs[n][132]
        int n = i >> 5, s4 = i & 31;
        float4 v = *(const float4*)(x + (size_t)n * NTOT + s0 + 4 * s4);
        *(uint4*)(r1 + n * 132 + 4 * s4) = cvt4(v);
    }
    for (int i = tid; i < 1024; i += 256) {               // lbs[q][t][36]
        int q = i >> 8, t = (i >> 3) & 31, s4 = i & 7;
        float4 v = *(const float4*)(lb + (size_t)(slice * 4 + q) * 1024 + t * 32 + 4 * s4);
        *(uint4*)(r2 + q * 1152 + t * 36 + 4 * s4) = cvt4(v);
    }
    __syncthreads();

    float acc[4][4];
    #pragma unroll
    for (int j = 0; j < 4; j++) { acc[j][0] = acc[j][1] = acc[j][2] = acc[j][3] = 0.f; }

    {   // leaf: warp n'-group wg == leaf block q
        const uint32_t* X = r1u + 16 * wm * 132 + 32 * wg;
        const uint32_t* Bq = r2u + wg * 1152;
        for (int kc = 0; kc < 4; kc++) {
            uint32_t a[4];
            int ko = 8 * kc + t4;
            a[0] = X[g * 132 + ko];     a[1] = X[(g + 8) * 132 + ko];
            a[2] = X[g * 132 + ko + 4]; a[3] = X[(g + 8) * 132 + ko + 4];
            #pragma unroll
            for (int j = 0; j < 4; j++) {
                int tl = 8 * j + g;
                mma8(acc[j], a, Bq[tl * 36 + ko], Bq[tl * 36 + ko + 4]);
            }
        }
    }

    #pragma unroll 1
    for (int L = 0; L < 12; L++) {
        int R = c_R[L], Rq = R >> 2;
        __syncthreads();
        if (L == 9 || L == 11) {                           // zero k-pad cols of us
            uint4 z = {0, 0, 0, 0};
            for (int i = tid; i < 2176; i += 256) ((uint4*)r1)[i] = z;
            __syncthreads();
        }
        const float* U = p.u[L];
        for (int i = tid; i < 128 * Rq; i += 256) {        // us[s][68]
            int s = i / Rq, r4 = i - s * Rq;
            float4 v = *(const float4*)(U + (size_t)(s0 + s) * R + 4 * r4);
            *(uint4*)(r1 + s * 68 + 4 * r4) = cvt4(v);
        }
        if (L <= 8) {                                      // ts[n][68]
            int sib = (slice >> (9 - L)) ^ 1;
            const float* tb = g_t + c_OFF[L] + (size_t)sib * 2048;
            for (int i = tid; i < 512; i += 256) {
                int n = i >> 4, r4 = i & 15;
                float4 v = *(const float4*)(tb + n * 64 + 4 * r4);
                v.x *= s2; v.y *= s2; v.z *= s2; v.w *= s2;
                *(uint4*)(r2 + n * 68 + 4 * r4) = cvt4(v);
            }
        } else if (L == 9) {
            int sib = slice ^ 1;
            const float* tb = g_t + c_OFF[9] + (size_t)sib * 1792;
            for (int i = tid; i < 448; i += 256) {
                int n = i / 14, r4 = i - n * 14;
                float4 v = *(const float4*)(tb + n * 56 + 4 * r4);
                v.x *= s2; v.y *= s2; v.z *= s2; v.w *= s2;
                *(uint4*)(r2 + n * 68 + 4 * r4) = cvt4(v);
            }
        } else if (L == 10) {                              // ts slots [j][n][36]
            for (int i = tid; i < 512; i += 256) {
                int j = i >> 8, n = (i >> 3) & 31, r4 = i & 7;
                const float* tb = g_t + c_OFF[10] + (size_t)(slice * 2 + (j ^ 1)) * 1024;
                float4 v = *(const float4*)(tb + n * 32 + 4 * r4);
                v.x *= s2; v.y *= s2; v.z *= s2; v.w *= s2;
                *(uint4*)(r2 + j * 1152 + n * 36 + 4 * r4) = cvt4(v);
            }
        } else {
            for (int i = tid; i < 768; i += 256) {
                int j = i / 192, rem = i - j * 192, n = rem / 6, r4 = rem - n * 6;
                const float* tb = g_t + c_OFF[11] + (size_t)(slice * 4 + (j ^ 1)) * 768;
                float4 v = *(const float4*)(tb + n * 24 + 4 * r4);
                v.x *= s2; v.y *= s2; v.z *= s2; v.w *= s2;
                *(uint4*)(r2 + j * 1152 + n * 36 + 4 * r4) = cvt4(v);
            }
        }
        __syncthreads();

        int astride = (L <= 9) ? 68 : 36;
        int nch = (L <= 8) ? 8 : (L == 9 ? 7 : (L == 10 ? 4 : 3));
        const uint32_t* A = r2u;
        if (L == 10) A = r2u + (wg >> 1) * 1152;
        else if (L == 11) A = r2u + wg * 1152;
        const uint32_t* Arow = A + 16 * wm * astride;
        const uint32_t* Bs = r1u + 32 * wg * 68;
        for (int kc = 0; kc < nch; kc++) {
            uint32_t a[4];
            int ko = 8 * kc + t4;
            a[0] = Arow[g * astride + ko];     a[1] = Arow[(g + 8) * astride + ko];
            a[2] = Arow[g * astride + ko + 4]; a[3] = Arow[(g + 8) * astride + ko + 4];
            #pragma unroll
            for (int j = 0; j < 4; j++) {
                int sl = 8 * j + g;
                mma8(acc[j], a, Bs[sl * 68 + ko], Bs[sl * 68 + ko + 4]);
            }
        }
    }

    int n1 = 16 * wm + g;
    #pragma unroll
    for (int j = 0; j < 4; j++) {
        int sl = s0 + 32 * wg + 8 * j + 2 * t4;
        *(float2*)(out + (size_t)n1 * NTOT + sl)       = make_float2(acc[j][0], acc[j][1]);
        *(float2*)(out + (size_t)(n1 + 8) * NTOT + sl) = make_float2(acc[j][2], acc[j][3]);
    }
}

// ---------- driver ----------
extern "C" void kernel_launch(void* const* d_in, const int* in_sizes, int n_in,
                              void* d_out, int out_size) {
    (void)in_sizes; (void)n_in; (void)out_size;
    const float* x  = (const float*)d_in[0];
    const float* lb = (const float*)d_in[1];
    const float* sc = (const float*)d_in[2];
    P p;
    for (int l = 0; l < 12; l++) p.u[l] = (const float*)d_in[3 + l];
    float* out = (float*)d_out;

    cudaFuncSetAttribute(k_p1,  cudaFuncAttributeMaxDynamicSharedMemorySize, P1_SM);
    cudaFuncSetAttribute(k_epi, cudaFuncAttributeMaxDynamicSharedMemorySize, E_SM);

    k_zero_t<<<(ZERON / 4 + 255) / 256, 256>>>();
    k_p1<<<1024, 256, P1_SM>>>(p, x);
    k_epi<<<1024, 256, E_SM>>>(p, lb, x, sc, out);
}

// round 11
// speedup vs baseline: 2.8647x; 1.5550x over previous
#include <cuda_runtime.h>
#include <cstdint>

#define NTOT 131072

__device__ __align__(16) float g_t[9170944];
__constant__ int c_OFF[12] = {0,4096,12288,28672,61440,126976,258048,520192,
                              1044480,2093056,3928064,6025216};
__constant__ int c_R[12] = {64,64,64,64,64,64,64,64,64,52,32,20};
__constant__ unsigned c_MUL[12] = {65536,65536,65536,65536,65536,65536,65536,65536,
                                   65536,80660,131072,209716};   // ceil(2^20/Rq)
#define ZERON 2093056   // levels 0-8 atomic region

struct P { const float* u[12]; };

// ---------- helpers ----------
__device__ __forceinline__ uint32_t cvtf32(float f) {
    uint32_t r; asm("cvt.rna.tf32.f32 %0, %1;" : "=r"(r) : "f"(f)); return r;
}
__device__ __forceinline__ uint4 cvt4(float4 v) {
    uint4 o; o.x = cvtf32(v.x); o.y = cvtf32(v.y); o.z = cvtf32(v.z); o.w = cvtf32(v.w);
    return o;
}
__device__ __forceinline__ uint4 cvt4s(float4 v, float s2) {
    uint4 o; o.x = cvtf32(v.x * s2); o.y = cvtf32(v.y * s2);
    o.z = cvtf32(v.z * s2); o.w = cvtf32(v.w * s2);
    return o;
}
__device__ __forceinline__ void mma8(float* c, const uint32_t* a, uint32_t b0, uint32_t b1) {
    asm volatile("mma.sync.aligned.m16n8k8.row.col.f32.tf32.tf32.f32 "
        "{%0,%1,%2,%3}, {%4,%5,%6,%7}, {%8,%9}, {%0,%1,%2,%3};"
        : "+f"(c[0]), "+f"(c[1]), "+f"(c[2]), "+f"(c[3])
        : "r"(a[0]), "r"(a[1]), "r"(a[2]), "r"(a[3]), "r"(b0), "r"(b1));
}

__global__ void k_zero_t() {
    int i = blockIdx.x * blockDim.x + threadIdx.x;
    if (i < ZERON / 4) ((float4*)g_t)[i] = make_float4(0.f, 0.f, 0.f, 0.f);
}

// ================= phase 1: t'[n][r-stack] = x[n][s] * U[s][r], per 128-s slice =================
// smem: xs [32][132] (A row-major), us [128][68] (B, tight; block-diag cols mod 2)
#define P1_SM ((4224 + 8704) * 4)
__global__ void __launch_bounds__(256, 2) k_p1(P p, const float* __restrict__ x) {
    extern __shared__ __align__(16) float sm[];
    float* xs = sm;
    float* us = sm + 4224;
    const uint32_t* xsu = (const uint32_t*)xs;
    const uint32_t* usu = (const uint32_t*)us;
    int tid = threadIdx.x, w = tid >> 5, lane = tid & 31;
    int g = lane >> 2, t4 = lane & 3;
    int wm = w >> 2, wg = w & 3;
    int slice = blockIdx.x, s0 = slice * 128;

    for (int i = tid; i < 1024; i += 256) {               // xs[n][132]
        int n = i >> 5, s4 = i & 31;
        float4 v = *(const float4*)(x + (size_t)n * NTOT + s0 + 4 * s4);
        *(uint4*)(xs + n * 132 + 4 * s4) = cvt4(v);
    }

    float4 pf[8];
    {   // prefetch U[0] (contiguous slice block)
        const float4* U0 = (const float4*)p.u[0] + (size_t)slice * 2048;
        #pragma unroll
        for (int it = 0; it < 8; it++) pf[it] = U0[tid + 256 * it];
    }

    #pragma unroll 1
    for (int L = 0; L < 12; L++) {
        int Rq = c_R[L] >> 2;
        int tot = 128 * Rq;
        unsigned MUL = c_MUL[L];
        __syncthreads();                                   // us free (prev compute done)
        uint4 z = {0, 0, 0, 0};
        if (L == 9 && tid < 128) *(uint4*)(us + tid * 68 + 52) = z;
        if (L == 11 && tid < 128) {
            *(uint4*)(us + tid * 68 + 20) = z;
            *(uint4*)(us + tid * 68 + 44) = z;
        }
        #pragma unroll
        for (int it = 0; it < 8; it++) {
            int i = tid + 256 * it;
            if (i < tot) {
                int s = (int)(((unsigned)i * MUL) >> 20);
                int r4 = i - s * Rq;
                int col = (L <= 9) ? 4 * r4
                        : (L == 10 ? ((s >> 6) & 1) * 32 + 4 * r4
                                   : ((s >> 5) & 1) * 24 + 4 * r4);
                *(uint4*)(us + s * 68 + col) = cvt4(pf[it]);
            }
        }
        __syncthreads();
        if (L < 11) {                                      // prefetch next level
            int tot2 = 128 * (c_R[L + 1] >> 2);
            const float4* U2 = (const float4*)p.u[L + 1] + (size_t)slice * tot2;
            #pragma unroll
            for (int it = 0; it < 8; it++) {
                int i = tid + 256 * it;
                if (i < tot2) pf[it] = U2[i];
            }
        }

        int ntile = (L == 11) ? 3 : 2;
        int nb = (L == 11) ? 24 * (wg & 1) : 16 * wg;
        int kc0 = 0, kc1 = 16;
        if (L == 10) { kc0 = 8 * (wg >> 1); kc1 = kc0 + 8; }
        if (L == 11) { kc0 = 4 * wg;        kc1 = kc0 + 4; }

        float acc[3][4];
        #pragma unroll
        for (int j = 0; j < 3; j++) { acc[j][0] = acc[j][1] = acc[j][2] = acc[j][3] = 0.f; }

        const uint32_t* X = xsu + 16 * wm * 132;
        for (int kc = kc0; kc < kc1; kc++) {
            uint32_t a[4];
            int ko = 8 * kc + t4;
            a[0] = X[g * 132 + ko];       a[1] = X[(g + 8) * 132 + ko];
            a[2] = X[g * 132 + ko + 4];   a[3] = X[(g + 8) * 132 + ko + 4];
            const uint32_t* B0 = usu + (8 * kc + t4) * 68;
            const uint32_t* B1 = usu + (8 * kc + t4 + 4) * 68;
            #pragma unroll
            for (int j = 0; j < 3; j++)
                if (j < ntile) {
                    int np = nb + 8 * j + g;
                    mma8(acc[j], a, B0[np], B1[np]);
                }
        }

        int n1 = 16 * wm + g;
        #pragma unroll
        for (int j = 0; j < 3; j++) {
            if (j < ntile) {
                int np = nb + 8 * j + 2 * t4;
                if (L <= 8) {
                    int blk = slice >> (9 - L);
                    float* d0 = g_t + c_OFF[L] + (size_t)blk * 2048;
                    atomicAdd(d0 + n1 * 64 + np,           acc[j][0]);
                    atomicAdd(d0 + n1 * 64 + np + 1,       acc[j][1]);
                    atomicAdd(d0 + (n1 + 8) * 64 + np,     acc[j][2]);
                    atomicAdd(d0 + (n1 + 8) * 64 + np + 1, acc[j][3]);
                } else if (L == 9) {
                    if (np < 56) {
                        float* d0 = g_t + c_OFF[9] + (size_t)slice * 1792;
                        *(float2*)(d0 + n1 * 56 + np)       = make_float2(acc[j][0], acc[j][1]);
                        *(float2*)(d0 + (n1 + 8) * 56 + np) = make_float2(acc[j][2], acc[j][3]);
                    }
                } else if (L == 10) {
                    int blk = slice * 2 + (np >> 5), r = np & 31;
                    float* d0 = g_t + c_OFF[10] + (size_t)blk * 1024;
                    *(float2*)(d0 + n1 * 32 + r)       = make_float2(acc[j][0], acc[j][1]);
                    *(float2*)(d0 + (n1 + 8) * 32 + r) = make_float2(acc[j][2], acc[j][3]);
                } else {
                    int blk = slice * 4 + wg, r = 8 * j + 2 * t4;
                    float* d0 = g_t + c_OFF[11] + (size_t)blk * 768;
                    *(float2*)(d0 + n1 * 24 + r)       = make_float2(acc[j][0], acc[j][1]);
                    *(float2*)(d0 + (n1 + 8) * 24 + r) = make_float2(acc[j][2], acc[j][3]);
                }
            }
        }
    }
}

// ---------- epilogue t-load helpers ----------
__device__ __forceinline__ int t_count(int L) {
    return (L <= 8 || L == 10) ? 512 : (L == 9 ? 448 : 768);
}
__device__ __forceinline__ float4 t_load(int L, int i, int slice) {
    const float4* b;
    if (L <= 8)      b = (const float4*)(g_t + c_OFF[L]) + (size_t)((slice >> (9 - L)) ^ 1) * 512 + i;
    else if (L == 9) b = (const float4*)(g_t + c_OFF[9]) + (size_t)(slice ^ 1) * 448 + i;
    else if (L == 10) {
        int j = i >> 8;
        b = (const float4*)(g_t + c_OFF[10]) + (size_t)(slice * 2 + (j ^ 1)) * 256 + (i & 255);
    } else {
        int j = i / 192;
        b = (const float4*)(g_t + c_OFF[11]) + (size_t)(slice * 4 + (j ^ 1)) * 192 + (i - 192 * j);
    }
    return *b;
}
__device__ __forceinline__ void t_store(float* r2, int L, int i, float4 v, float s2) {
    int off;
    if (L <= 8)      { int n = i >> 4, r4 = i & 15;            off = n * 68 + 4 * r4; }
    else if (L == 9) { int n = (int)(((unsigned)i * 74899u) >> 20); int r4 = i - 14 * n;
                       off = n * 68 + 4 * r4; }
    else if (L == 10){ int j = i >> 8, n = (i >> 3) & 31, r4 = i & 7;
                       off = j * 1152 + n * 36 + 4 * r4; }
    else             { int j = i / 192, rem = i - 192 * j;
                       int n = (int)(((unsigned)rem * 174763u) >> 20); int r4 = rem - 6 * n;
                       off = j * 1152 + n * 36 + 4 * r4; }
    *(uint4*)(r2 + off) = cvt4s(v, s2);
}

// ================= epilogue: out[n][s] = leaf + sum_L t_sib[n][r] * U[s][r] =================
#define E_SM ((8704 + 4608) * 4)
__global__ void __launch_bounds__(256, 2) k_epi(P p, const float* __restrict__ lb,
                                                const float* __restrict__ x,
                                                const float* __restrict__ sc,
                                                float* __restrict__ out) {
    extern __shared__ __align__(16) float sm[];
    float* r1 = sm;
    float* r2 = sm + 8704;
    const uint32_t* r1u = (const uint32_t*)r1;
    const uint32_t* r2u = (const uint32_t*)r2;
    int tid = threadIdx.x, w = tid >> 5, lane = tid & 31;
    int g = lane >> 2, t4 = lane & 3;
    int wm = w >> 2, wg = w & 3;
    int slice = blockIdx.x, s0 = slice * 128;
    float scv = __ldg(sc), s2 = scv * scv;

    for (int i = tid; i < 1024; i += 256) {               // xs[n][132]
        int n = i >> 5, s4 = i & 31;
        float4 v = *(const float4*)(x + (size_t)n * NTOT + s0 + 4 * s4);
        *(uint4*)(r1 + n * 132 + 4 * s4) = cvt4(v);
    }
    for (int i = tid; i < 1024; i += 256) {               // lbs[q][t][36]
        int q = i >> 8, t = (i >> 3) & 31, s4 = i & 7;
        float4 v = *(const float4*)(lb + (size_t)(slice * 4 + q) * 1024 + t * 32 + 4 * s4);
        *(uint4*)(r2 + q * 1152 + t * 36 + 4 * s4) = cvt4(v);
    }

    float4 pf[8];
    float4 pt[3];
    {   // prefetch U[0], t[0]
        const float4* U0 = (const float4*)p.u[0] + (size_t)slice * 2048;
        #pragma unroll
        for (int it = 0; it < 8; it++) pf[it] = U0[tid + 256 * it];
        #pragma unroll
        for (int it = 0; it < 3; it++) {
            int i = tid + 256 * it;
            if (i < 512) pt[it] = t_load(0, i, slice);
        }
    }
    __syncthreads();

    float acc[4][4];
    #pragma unroll
    for (int j = 0; j < 4; j++) { acc[j][0] = acc[j][1] = acc[j][2] = acc[j][3] = 0.f; }

    {   // leaf: warp n'-group wg == leaf block q
        const uint32_t* X = r1u + 16 * wm * 132 + 32 * wg;
        const uint32_t* Bq = r2u + wg * 1152;
        for (int kc = 0; kc < 4; kc++) {
            uint32_t a[4];
            int ko = 8 * kc + t4;
            a[0] = X[g * 132 + ko];     a[1] = X[(g + 8) * 132 + ko];
            a[2] = X[g * 132 + ko + 4]; a[3] = X[(g + 8) * 132 + ko + 4];
            #pragma unroll
            for (int j = 0; j < 4; j++) {
                int tl = 8 * j + g;
                mma8(acc[j], a, Bq[tl * 36 + ko], Bq[tl * 36 + ko + 4]);
            }
        }
    }

    #pragma unroll 1
    for (int L = 0; L < 12; L++) {
        int Rq = c_R[L] >> 2;
        int tot = 128 * Rq;
        unsigned MUL = c_MUL[L];
        __syncthreads();                                   // buffers free
        uint4 z = {0, 0, 0, 0};
        if (L == 9 && tid < 128)  *(uint4*)(r1 + tid * 68 + 52) = z;
        if (L == 11 && tid < 128) *(uint4*)(r1 + tid * 68 + 20) = z;
        #pragma unroll
        for (int it = 0; it < 8; it++) {                   // STS U[L]
            int i = tid + 256 * it;
            if (i < tot) {
                int s = (int)(((unsigned)i * MUL) >> 20);
                int r4 = i - s * Rq;
                *(uint4*)(r1 + s * 68 + 4 * r4) = cvt4(pf[it]);
            }
        }
        int tcnt = t_count(L);
        #pragma unroll
        for (int it = 0; it < 3; it++) {                   // STS t[L] (scaled)
            int i = tid + 256 * it;
            if (i < tcnt) t_store(r2, L, i, pt[it], s2);
        }
        __syncthreads();
        if (L < 11) {                                      // prefetch next
            int tot2 = 128 * (c_R[L + 1] >> 2);
            const float4* U2 = (const float4*)p.u[L + 1] + (size_t)slice * tot2;
            #pragma unroll
            for (int it = 0; it < 8; it++) {
                int i = tid + 256 * it;
                if (i < tot2) pf[it] = U2[i];
            }
            int tc2 = t_count(L + 1);
            #pragma unroll
            for (int it = 0; it < 3; it++) {
                int i = tid + 256 * it;
                if (i < tc2) pt[it] = t_load(L + 1, i, slice);
            }
        }

        int astride = (L <= 9) ? 68 : 36;
        int nch = (L <= 8) ? 8 : (L == 9 ? 7 : (L == 10 ? 4 : 3));
        const uint32_t* A = r2u;
        if (L == 10) A = r2u + (wg >> 1) * 1152;
        else if (L == 11) A = r2u + wg * 1152;
        const uint32_t* Arow = A + 16 * wm * astride;
        const uint32_t* Bs = r1u + 32 * wg * 68;
        for (int kc = 0; kc < nch; kc++) {
            uint32_t a[4];
            int ko = 8 * kc + t4;
            a[0] = Arow[g * astride + ko];     a[1] = Arow[(g + 8) * astride + ko];
            a[2] = Arow[g * astride + ko + 4]; a[3] = Arow[(g + 8) * astride + ko + 4];
            #pragma unroll
            for (int j = 0; j < 4; j++) {
                int sl = 8 * j + g;
                mma8(acc[j], a, Bs[sl * 68 + ko], Bs[sl * 68 + ko + 4]);
            }
        }
    }

    int n1 = 16 * wm + g;
    #pragma unroll
    for (int j = 0; j < 4; j++) {
        int sl = s0 + 32 * wg + 8 * j + 2 * t4;
        *(float2*)(out + (size_t)n1 * NTOT + sl)       = make_float2(acc[j][0], acc[j][1]);
        *(float2*)(out + (size_t)(n1 + 8) * NTOT + sl) = make_float2(acc[j][2], acc[j][3]);
    }
}

// ---------- driver ----------
extern "C" void kernel_launch(void* const* d_in, const int* in_sizes, int n_in,
                              void* d_out, int out_size) {
    (void)in_sizes; (void)n_in; (void)out_size;
    const float* x  = (const float*)d_in[0];
    const float* lb = (const float*)d_in[1];
    const float* sc = (const float*)d_in[2];
    P p;
    for (int l = 0; l < 12; l++) p.u[l] = (const float*)d_in[3 + l];
    float* out = (float*)d_out;

    cudaFuncSetAttribute(k_p1,  cudaFuncAttributeMaxDynamicSharedMemorySize, P1_SM);
    cudaFuncSetAttribute(k_epi, cudaFuncAttributeMaxDynamicSharedMemorySize, E_SM);

    k_zero_t<<<(ZERON / 4 + 255) / 256, 256>>>();
    k_p1<<<1024, 256, P1_SM>>>(p, x);
    k_epi<<<1024, 256, E_SM>>>(p, lb, x, sc, out);
}